// round 16
// baseline (speedup 1.0000x reference)
#include <cuda_runtime.h>
#include <cstdint>

// out[b,c,h,w] = max over 4 directional 3x3 Laplacians (zero-padded).
// out = max(s0,s1,s2,s3) - 2*c  (shared center term -> single FFMA).
// Input: depth-1 register pipeline (4 rotating 6-float windows), RPT=16,
//        128-thread full-row blocks -> grid 1536 = single wave.
// Output: staged in double-buffered smem (2 x 4 rows x 2KB) and drained with
//        cp.async.bulk (8KB contiguous per op) -- stores leave the warp
//        pipeline and the read/write streams stop sharing the LSU/L1 path.

#define W   512
#define H   512
#define RPT 16   // rows per thread

__device__ __forceinline__ uint32_t smem_u32(const void* p) {
    uint32_t r;
    asm("{ .reg .u64 t; cvta.to.shared.u64 t, %1; cvt.u32.u64 %0, t; }"
        : "=r"(r) : "l"(p));
    return r;
}
__device__ __forceinline__ void bulk_store(void* gdst, uint32_t ssrc, uint32_t bytes) {
    asm volatile("cp.async.bulk.global.shared::cta.bulk_group [%0], [%1], %2;"
                 :: "l"(gdst), "r"(ssrc), "r"(bytes) : "memory");
    asm volatile("cp.async.bulk.commit_group;" ::: "memory");
}
template <int N>
__device__ __forceinline__ void bulk_wait() {
    asm volatile("cp.async.bulk.wait_group %0;" :: "n"(N) : "memory");
}

// Load 6-wide window [w0-1 .. w0+4] of row h, zero-padded.
__device__ __forceinline__ void load_row6(const float* __restrict__ img,
                                          int h, int w0, float a[6]) {
    if ((unsigned)h >= (unsigned)H) {
        #pragma unroll
        for (int i = 0; i < 6; i++) a[i] = 0.f;
        return;
    }
    const float* row = img + h * W;
    float4 v = __ldg((const float4*)(row + w0));
    a[1] = v.x; a[2] = v.y; a[3] = v.z; a[4] = v.w;
    a[0] = (w0 > 0)     ? __ldg(row + w0 - 1) : 0.f;  // same-line L1/L2 hit
    a[5] = (w0 + 4 < W) ? __ldg(row + w0 + 4) : 0.f;
}

__global__ __launch_bounds__(128, 11)
void maxlap_kernel(const float* __restrict__ x, float* __restrict__ out) {
    __shared__ __align__(128) float obuf[2][4][W];   // 16KB double buffer

    const int tid = threadIdx.x;
    const int img = blockIdx.y;
    const int h0  = blockIdx.x * RPT;
    const int w0  = tid * 4;            // 128 threads cover the full 512 row

    const float* in  = x   + (size_t)img * H * W;
    float*       dst = out + (size_t)img * H * W;

    // Depth-1 pipeline: t=win[rr&3], m=win[(rr+1)&3], b=win[(rr+2)&3];
    // row h0+rr+2 prefetches into win[(rr+3)&3].
    float win[4][6];
    load_row6(in, h0 - 1, w0, win[0]);
    load_row6(in, h0,     w0, win[1]);
    load_row6(in, h0 + 1, w0, win[2]);

    #pragma unroll
    for (int rr = 0; rr < RPT; rr++) {
        if (rr < RPT - 1)
            load_row6(in, h0 + rr + 2, w0, win[(rr + 3) & 3]);  // prefetch

        const float* t = win[ rr      & 3];
        const float* m = win[(rr + 1) & 3];
        const float* b = win[(rr + 2) & 3];

        float4 o;
        float* op = (float*)&o;
        #pragma unroll
        for (int i = 0; i < 4; i++) {
            const float s0 = m[i]     + m[i + 2];
            const float s1 = t[i + 1] + b[i + 1];
            const float s2 = t[i + 2] + b[i];
            const float s3 = t[i]     + b[i + 2];
            const float ms = fmaxf(fmaxf(s0, s1), fmaxf(s2, s3));
            op[i] = fmaf(-2.f, m[i + 1], ms);
        }
        *(float4*)(&obuf[(rr >> 2) & 1][rr & 3][w0]) = o;   // STS.128

        if ((rr & 3) == 3) {
            // Make STS visible to the async proxy, then drain 4 rows (8KB).
            asm volatile("fence.proxy.async.shared::cta;" ::: "memory");
            __syncthreads();
            if (tid == 0) {
                bulk_store(dst + (size_t)(h0 + rr - 3) * W,
                           smem_u32(&obuf[(rr >> 2) & 1][0][0]), 4 * W * 4);
                bulk_wait<1>();      // previous chunk done -> other buffer free
            }
            __syncthreads();
        }
    }

    // Keep the CTA alive until the last bulk read of smem has completed.
    if (tid == 0) bulk_wait<0>();
}

extern "C" void kernel_launch(void* const* d_in, const int* in_sizes, int n_in,
                              void* d_out, int out_size) {
    const float* x = (const float*)d_in[0];
    float* out = (float*)d_out;

    const int n_img = in_sizes[0] / (H * W);  // B*C = 48

    dim3 block(W / 4);               // 128 threads = one full row
    dim3 grid(H / RPT, n_img);       // 32 x 48 = 1536 blocks (single wave)
    maxlap_kernel<<<grid, block>>>(x, out);
}

// round 17
// speedup vs baseline: 1.1863x; 1.1863x over previous
#include <cuda_runtime.h>
#include <cstdint>

// out[b,c,h,w] = max over 4 directional 3x3 Laplacians (zero-padded).
// out = max(s0,s1,s2,s3) - 2*c  (shared center term -> single FFMA).
// Depth-1 register pipeline (4 rotating windows), RPT=16 -> single wave.
// Halos: ONE merged predicated edge LDG at load time (lanes 0/31 only);
// interior halo slots filled by shuffle at USE time (one iteration after the
// LDG -> prefetch distance preserved). Pointer-increment addressing.

#define W   512
#define H   512
#define RPT 16   // rows per thread

// Load the float4 + merged edge halo of row (base row pointer), no shuffles.
__device__ __forceinline__ void load_row(const float* rowp, bool valid,
                                         int w0, int lane, float a[6]) {
    if (!valid) {
        #pragma unroll
        for (int i = 0; i < 6; i++) a[i] = 0.f;
        return;
    }
    float4 v = __ldg((const float4*)(rowp + w0));
    a[1] = v.x; a[2] = v.y; a[3] = v.z; a[4] = v.w;

    float hv = 0.f;
    const bool left  = (lane == 0)  && (w0 > 0);
    const bool right = (lane == 31) && (w0 + 4 < W);
    if (left || right)
        hv = __ldg(rowp + (left ? (w0 - 1) : (w0 + 4)));
    a[0] = hv;   // valid on lane 0 only; interior lanes patched at use time
    a[5] = hv;   // valid on lane 31 only
}

// Patch interior halo slots from neighbor lanes' registers (loaded >=1 iter ago).
__device__ __forceinline__ void patch(int lane, float a[6]) {
    const float l = __shfl_up_sync(0xffffffffu, a[4], 1);
    const float r = __shfl_down_sync(0xffffffffu, a[1], 1);
    if (lane != 0)  a[0] = l;
    if (lane != 31) a[5] = r;
}

__global__ __launch_bounds__(128, 12)
void maxlap_kernel(const float* __restrict__ x, float* __restrict__ out) {
    const int tid  = threadIdx.x;
    const int lane = tid & 31;
    const int img  = blockIdx.y;
    const int h0   = blockIdx.x * RPT;
    const int w0   = tid * 4;           // 128 threads cover the full 512 row

    const float* in  = x   + (size_t)img * H * W;
    float*       dst = out + (size_t)img * H * W + (size_t)h0 * W + w0;

    // Rolling row pointer for the prefetch stream (row h0+1 upward).
    const float* rp = in + (size_t)(h0 + 1) * W;

    float win[4][6];
    load_row(in + (size_t)(h0 - 1) * W, h0 > 0, w0, lane, win[0]);
    load_row(in + (size_t)h0 * W,       true,   w0, lane, win[1]);
    load_row(rp,                        true,   w0, lane, win[2]);
    patch(lane, win[0]);
    patch(lane, win[1]);

    #pragma unroll
    for (int rr = 0; rr < RPT; rr++) {
        if (rr < RPT - 1) {
            rp += W;
            load_row(rp, (h0 + rr + 2) < H, w0, lane, win[(rr + 3) & 3]);  // prefetch
        }

        patch(lane, win[(rr + 2) & 3]);   // b row, loaded last iteration

        const float* t = win[ rr      & 3];
        const float* m = win[(rr + 1) & 3];
        const float* b = win[(rr + 2) & 3];

        float4 o;
        float* op = (float*)&o;
        #pragma unroll
        for (int i = 0; i < 4; i++) {
            const float s0 = m[i]     + m[i + 2];
            const float s1 = t[i + 1] + b[i + 1];
            const float s2 = t[i + 2] + b[i];
            const float s3 = t[i]     + b[i + 2];
            const float ms = fmaxf(fmaxf(s0, s1), fmaxf(s2, s3));
            op[i] = fmaf(-2.f, m[i + 1], ms);
        }
        __stcs((float4*)dst, o);          // streaming store
        dst += W;
    }
}

extern "C" void kernel_launch(void* const* d_in, const int* in_sizes, int n_in,
                              void* d_out, int out_size) {
    const float* x = (const float*)d_in[0];
    float* out = (float*)d_out;

    const int n_img = in_sizes[0] / (H * W);  // B*C = 48

    dim3 block(W / 4);               // 128 threads = one full row
    dim3 grid(H / RPT, n_img);       // 32 x 48 = 1536 blocks (single wave)
    maxlap_kernel<<<grid, block>>>(x, out);
}